// round 2
// baseline (speedup 1.0000x reference)
#include <cuda_runtime.h>

// Inverse discrete Hough transform:
// out[nc, y, x] = sum_a acc[nc, a, r(a,y,x)],  r = round(xc*cos + yc*sin) + 200
// nc = n*64+c (256 slices), A=180, R=400, H=W=256.
//
// Strategy:
//  1) trig kernel computes cos/sin via DOUBLE precision (immune to
//     --use_fast_math; gives correctly-rounded f32, matching the JAX ref).
//  2) transpose acc[nc][a*400+r] -> accT[a*400+r][nc]  (nc contiguous, 1KB rows)
//  3) main kernel: one warp per (y,x); r is warp-uniform; 2x LDG.128 per angle
//     fetch the whole 256-channel row; 8 fp32 accumulators per lane.
//     Output staged through smem so global writes are fully coalesced.

#define NUMANGLE 180
#define NUMRHO   400
#define NC       256
#define OH       256
#define OW       256
#define AR       (NUMANGLE * NUMRHO)   // 72000

__device__ float  g_accT[AR * NC];     // 73.7 MB transposed accumulator
__device__ float2 g_trig[NUMANGLE];

__global__ void k_trig() {
    int a = threadIdx.x;
    if (a < NUMANGLE) {
        // match reference: theta = f32(a) * f32(np.pi/180), f32 multiply,
        // then correctly-rounded f32 cos/sin of that f32 theta (via double —
        // NOT cosf/sinf, which fast-math degrades to MUFU approximations).
        float t = __fmul_rn((float)a, (float)(3.14159265358979323846 / 180.0));
        double td = (double)t;
        g_trig[a] = make_float2((float)cos(td), (float)sin(td));
    }
}

// 32x32 tiled transpose of M[256][72000] -> MT[72000][256]
__global__ void k_transpose(const float* __restrict__ in) {
    __shared__ float tile[32][33];
    int tx = threadIdx.x, ty = threadIdx.y;           // 32 x 8
    int ar = blockIdx.x * 32 + tx;
#pragma unroll
    for (int k = 0; k < 4; k++) {
        int nc = blockIdx.y * 32 + ty + k * 8;
        tile[ty + k * 8][tx] = in[(size_t)nc * AR + ar];
    }
    __syncthreads();
    int nc2 = blockIdx.y * 32 + tx;
#pragma unroll
    for (int k = 0; k < 4; k++) {
        int ar2 = blockIdx.x * 32 + ty + k * 8;
        g_accT[(size_t)ar2 * NC + nc2] = tile[tx][ty + k * 8];
    }
}

__global__ __launch_bounds__(256) void k_main(float* __restrict__ out) {
    __shared__ float2 trig[NUMANGLE];
    __shared__ float  st[8][NC];       // 8 (y,x) positions x 256 channels

    int tid = threadIdx.x;
    if (tid < NUMANGLE) trig[tid] = g_trig[tid];
    __syncthreads();

    int w = tid >> 5;                  // warp id -> x within tile of 8
    int l = tid & 31;                  // lane -> channel group
    int x = blockIdx.x * 8 + w;
    int y = blockIdx.y;

    float xc = (float)(x - OW / 2);
    float yc = (float)(y - OH / 2);

    float4 a0 = make_float4(0.f, 0.f, 0.f, 0.f);
    float4 a1 = make_float4(0.f, 0.f, 0.f, 0.f);

    // r is ALWAYS in range for these shapes: |xc*cos+yc*sin| <= 128*sqrt(2) < 200
#pragma unroll 4
    for (int a = 0; a < NUMANGLE; a++) {
        float2 cs = trig[a];
        // exact match to reference: rn(rn(xc*cos) + rn(yc*sin)), round-half-even
        float s = __fadd_rn(__fmul_rn(xc, cs.x), __fmul_rn(yc, cs.y));
        int   r = __float2int_rn(s) + NUMRHO / 2;
        const float4* rp =
            reinterpret_cast<const float4*>(g_accT + ((a * NUMRHO + r) << 8)) + l;
        float4 v0 = __ldg(rp);
        float4 v1 = __ldg(rp + 32);
        a0.x += v0.x; a0.y += v0.y; a0.z += v0.z; a0.w += v0.w;
        a1.x += v1.x; a1.y += v1.y; a1.z += v1.z; a1.w += v1.w;
    }

    // stage through smem so the global writes are coalesced per 128B line
    float4* st4 = reinterpret_cast<float4*>(&st[w][0]);
    st4[l]      = a0;   // channels [4l, 4l+4)
    st4[32 + l] = a1;   // channels [128+4l, 128+4l+4)
    __syncthreads();

    // thread tid == channel nc; gather its 8 x-values and store two float4s
    float v[8];
#pragma unroll
    for (int i = 0; i < 8; i++) v[i] = st[i][tid];
    float4* op = reinterpret_cast<float4*>(
        out + (size_t)tid * (OH * OW) + (size_t)y * OW + blockIdx.x * 8);
    op[0] = make_float4(v[0], v[1], v[2], v[3]);
    op[1] = make_float4(v[4], v[5], v[6], v[7]);
}

extern "C" void kernel_launch(void* const* d_in, const int* in_sizes, int n_in,
                              void* d_out, int out_size) {
    const float* acc = (const float*)d_in[0];
    float* out = (float*)d_out;

    k_trig<<<1, 192>>>();

    dim3 tb(32, 8);
    dim3 tg(AR / 32, NC / 32);         // 2250 x 8
    k_transpose<<<tg, tb>>>(acc);

    dim3 mg(OW / 8, OH);               // 32 x 256
    k_main<<<mg, 256>>>(out);
}